// round 4
// baseline (speedup 1.0000x reference)
#include <cuda_runtime.h>
#include <math.h>

// Problem constants
#define BB 64
#define JJ 42
#define PP 16384
#define JG 3            // joint groups
#define JT 14           // joints per group (JG*JT == JJ)
#define PC 4            // P chunks
#define PPB (PP/PC)     // 4096 points per block
#define THREADS 256
#define PPT (PPB/THREADS)   // 16 points per thread
#define NWARP (THREADS/32)
#define GRID (BB*JG*PC)     // 768 blocks
#define NBJ (BB*JJ)         // 2688
#define TAILK ((NBJ + THREADS - 1) / THREADS)  // 11

// Scratch: per-(b,j) partial min-squared-distance, one slot per P-chunk.
__device__ float g_partial[BB * JJ * PC];
__device__ unsigned int g_count;   // zero at module load; last block resets to 0

__global__ __launch_bounds__(THREADS, 2) void sdl_fused_kernel(
    const float* __restrict__ pred,   // [B,J,3]
    const float* __restrict__ pts,    // [B,P,3]
    const float* __restrict__ gt,     // [B,J]
    float* __restrict__ out)
{
    const int blk = blockIdx.x;
    const int pc = blk % PC;
    const int jg = (blk / PC) % JG;
    const int b  = blk / (PC * JG);
    const int t  = threadIdx.x;

    // Joint constants in registers. a2 is NOT kept live (recomputed in epilogue).
    float mx[JT], my[JT], mz[JT], acc[JT];
    const float* jp = pred + (size_t)(b * JJ + jg * JT) * 3;
#pragma unroll
    for (int j = 0; j < JT; j++) {
        mx[j] = -2.0f * jp[j * 3 + 0];
        my[j] = -2.0f * jp[j * 3 + 1];
        mz[j] = -2.0f * jp[j * 3 + 2];
        acc[j] = 3.0e38f;
    }

    // Points for this (b, pc): 4096 points via aligned float4 loads.
    const float4* p4 = (const float4*)(pts + ((size_t)b * PP + (size_t)pc * PPB) * 3);

#pragma unroll
    for (int it = 0; it < PPT / 4; it++) {
        // 4 points = 12 floats = 3 float4 loads
        const int f4 = it * (THREADS * 3) + t * 3;
        float4 A  = p4[f4 + 0];
        float4 Bv = p4[f4 + 1];
        float4 C  = p4[f4 + 2];

        float px[4], py[4], pz[4], b2[4];
        px[0] = A.x;  py[0] = A.y;  pz[0] = A.z;
        px[1] = A.w;  py[1] = Bv.x; pz[1] = Bv.y;
        px[2] = Bv.z; py[2] = Bv.w; pz[2] = C.x;
        px[3] = C.y;  py[3] = C.z;  pz[3] = C.w;
#pragma unroll
        for (int q = 0; q < 4; q++)
            b2[q] = fmaf(pz[q], pz[q], fmaf(py[q], py[q], px[q] * px[q]));

#pragma unroll
        for (int j = 0; j < JT; j++) {
            float t0 = fmaf(mz[j], pz[0], b2[0]);
            float t1 = fmaf(mz[j], pz[1], b2[1]);
            float t2 = fmaf(mz[j], pz[2], b2[2]);
            float t3 = fmaf(mz[j], pz[3], b2[3]);
            t0 = fmaf(my[j], py[0], t0);
            t1 = fmaf(my[j], py[1], t1);
            t2 = fmaf(my[j], py[2], t2);
            t3 = fmaf(my[j], py[3], t3);
            t0 = fmaf(mx[j], px[0], t0);
            t1 = fmaf(mx[j], px[1], t1);
            t2 = fmaf(mx[j], px[2], t2);
            t3 = fmaf(mx[j], px[3], t3);
            acc[j] = fminf(acc[j], fminf(fminf(t0, t1), fminf(t2, t3)));
        }
    }

    // Epilogue: fold |a|^2 (recompute from pred; constant shift commutes with min).
#pragma unroll
    for (int j = 0; j < JT; j++) {
        float ax = jp[j * 3 + 0];
        float ay = jp[j * 3 + 1];
        float az = jp[j * 3 + 2];
        acc[j] += fmaf(az, az, fmaf(ay, ay, ax * ax));
    }

    // Warp min-reduce.
#pragma unroll
    for (int j = 0; j < JT; j++) {
        float v = acc[j];
        v = fminf(v, __shfl_xor_sync(0xFFFFFFFFu, v, 16));
        v = fminf(v, __shfl_xor_sync(0xFFFFFFFFu, v, 8));
        v = fminf(v, __shfl_xor_sync(0xFFFFFFFFu, v, 4));
        v = fminf(v, __shfl_xor_sync(0xFFFFFFFFu, v, 2));
        v = fminf(v, __shfl_xor_sync(0xFFFFFFFFu, v, 1));
        acc[j] = v;
    }

    __shared__ float smin[NWARP][JT];
    const int w = t >> 5, l = t & 31;
    if (l == 0) {
#pragma unroll
        for (int j = 0; j < JT; j++) smin[w][j] = acc[j];
    }
    __syncthreads();

    if (t < JT) {
        float v = smin[0][t];
#pragma unroll
        for (int wi = 1; wi < NWARP; wi++) v = fminf(v, smin[wi][t]);
        g_partial[(size_t)(b * JJ + jg * JT + t) * PC + pc] = v;
    }

    // ---- last-block finalize (fused MSE) ----
    __threadfence();
    __syncthreads();
    __shared__ unsigned s_last;
    if (t == 0) {
        unsigned c = atomicAdd(&g_count, 1u);
        s_last = (c == (unsigned)(GRID - 1)) ? 1u : 0u;
    }
    __syncthreads();
    if (s_last == 0u) return;

    // Last block: all partials globally visible. Batch all loads first (MLP).
    const float4* gp = (const float4*)g_partial;
    float4 pv[TAILK];
    float  gv[TAILK];
#pragma unroll
    for (int k = 0; k < TAILK; k++) {
        int i = t + k * THREADS;
        bool ok = (i < NBJ);
        pv[k] = ok ? __ldcg(gp + i) : make_float4(0.f, 0.f, 0.f, 0.f);
        gv[k] = ok ? gt[i] : 0.f;
    }
    float s = 0.0f;
#pragma unroll
    for (int k = 0; k < TAILK; k++) {
        int i = t + k * THREADS;
        if (i < NBJ) {
            float m = fminf(fminf(pv[k].x, pv[k].y), fminf(pv[k].z, pv[k].w));
            m = fmaxf(m, 0.0f);
            float d = sqrtf(m) - gv[k];
            s = fmaf(d, d, s);
        }
    }
    // Deterministic fixed-order reduction.
    s += __shfl_xor_sync(0xFFFFFFFFu, s, 16);
    s += __shfl_xor_sync(0xFFFFFFFFu, s, 8);
    s += __shfl_xor_sync(0xFFFFFFFFu, s, 4);
    s += __shfl_xor_sync(0xFFFFFFFFu, s, 2);
    s += __shfl_xor_sync(0xFFFFFFFFu, s, 1);
    __shared__ float ssum[NWARP];
    if (l == 0) ssum[w] = s;
    __syncthreads();
    if (t == 0) {
        float tot = ssum[0];
#pragma unroll
        for (int wi = 1; wi < NWARP; wi++) tot += ssum[wi];
        out[0] = tot / (float)NBJ;
        g_count = 0;   // reset for next graph replay
    }
}

extern "C" void kernel_launch(void* const* d_in, const int* in_sizes, int n_in,
                              void* d_out, int out_size) {
    (void)in_sizes; (void)n_in; (void)out_size;
    const float* pred = (const float*)d_in[0];   // [64,42,3]
    const float* pts  = (const float*)d_in[1];   // [64,16384,3]
    const float* gt   = (const float*)d_in[2];   // [64,42]
    float* out = (float*)d_out;

    sdl_fused_kernel<<<GRID, THREADS>>>(pred, pts, gt, out);
}

// round 5
// speedup vs baseline: 1.4093x; 1.4093x over previous
#include <cuda_runtime.h>
#include <math.h>

// Problem constants
#define BB 64
#define JJ 42
#define PP 16384
#define JG 3            // joint groups
#define JT 14           // joints per group (JG*JT == JJ)
#define PC 4            // P chunks
#define PPB (PP/PC)     // 4096 points per block
#define THREADS 256
#define PPT (PPB/THREADS)   // 16 points per thread
#define NWARP (THREADS/32)
#define GRID (BB*JG*PC)     // 768 blocks
#define NBJ (BB*JJ)         // 2688
#define TAILK ((NBJ + THREADS - 1) / THREADS)  // 11

// Scratch: per-(b,j) partial min-squared-distance, one slot per P-chunk.
__device__ float g_partial[BB * JJ * PC];
__device__ unsigned int g_count;   // zero at module load; last block resets to 0

__global__ __launch_bounds__(THREADS, 2) void sdl_fused_kernel(
    const float* __restrict__ pred,   // [B,J,3]
    const float* __restrict__ pts,    // [B,P,3]
    const float* __restrict__ gt,     // [B,J]
    float* __restrict__ out)
{
    const int blk = blockIdx.x;
    const int pc = blk % PC;
    const int jg = (blk / PC) % JG;
    const int b  = blk / (PC * JG);
    const int t  = threadIdx.x;

    // Joint constants in registers (a2 recomputed in epilogue, not kept live).
    float mx[JT], my[JT], mz[JT], acc[JT];
    const float* jp = pred + (size_t)(b * JJ + jg * JT) * 3;
#pragma unroll
    for (int j = 0; j < JT; j++) {
        mx[j] = -2.0f * jp[j * 3 + 0];
        my[j] = -2.0f * jp[j * 3 + 1];
        mz[j] = -2.0f * jp[j * 3 + 2];
        acc[j] = 3.0e38f;
    }

    // Points for this (b, pc): 4096 points via aligned float4 loads.
    const float4* p4 = (const float4*)(pts + ((size_t)b * PP + (size_t)pc * PPB) * 3);

    // unroll 1: keep exactly one iteration's points live (no hoisted-LDG spills).
#pragma unroll 1
    for (int it = 0; it < PPT / 4; it++) {
        // 4 points = 12 floats = 3 float4 loads
        const int f4 = it * (THREADS * 3) + t * 3;
        float4 A  = p4[f4 + 0];
        float4 Bv = p4[f4 + 1];
        float4 C  = p4[f4 + 2];

        float px[4], py[4], pz[4], b2[4];
        px[0] = A.x;  py[0] = A.y;  pz[0] = A.z;
        px[1] = A.w;  py[1] = Bv.x; pz[1] = Bv.y;
        px[2] = Bv.z; py[2] = Bv.w; pz[2] = C.x;
        px[3] = C.y;  py[3] = C.z;  pz[3] = C.w;
#pragma unroll
        for (int q = 0; q < 4; q++)
            b2[q] = fmaf(pz[q], pz[q], fmaf(py[q], py[q], px[q] * px[q]));

#pragma unroll
        for (int q = 0; q < 4; q++) {
#pragma unroll
            for (int j = 0; j < JT; j++) {
                float tq = fmaf(mx[j], px[q],
                            fmaf(my[j], py[q],
                             fmaf(mz[j], pz[q], b2[q])));
                acc[j] = fminf(acc[j], tq);
            }
        }
    }

    // Epilogue: fold |a|^2 (recompute from pred; constant shift commutes with min).
#pragma unroll
    for (int j = 0; j < JT; j++) {
        float ax = jp[j * 3 + 0];
        float ay = jp[j * 3 + 1];
        float az = jp[j * 3 + 2];
        acc[j] += fmaf(az, az, fmaf(ay, ay, ax * ax));
    }

    // Warp min-reduce.
#pragma unroll
    for (int j = 0; j < JT; j++) {
        float v = acc[j];
        v = fminf(v, __shfl_xor_sync(0xFFFFFFFFu, v, 16));
        v = fminf(v, __shfl_xor_sync(0xFFFFFFFFu, v, 8));
        v = fminf(v, __shfl_xor_sync(0xFFFFFFFFu, v, 4));
        v = fminf(v, __shfl_xor_sync(0xFFFFFFFFu, v, 2));
        v = fminf(v, __shfl_xor_sync(0xFFFFFFFFu, v, 1));
        acc[j] = v;
    }

    __shared__ float smin[NWARP][JT];
    const int w = t >> 5, l = t & 31;
    if (l == 0) {
#pragma unroll
        for (int j = 0; j < JT; j++) smin[w][j] = acc[j];
    }
    __syncthreads();

    if (t < JT) {
        float v = smin[0][t];
#pragma unroll
        for (int wi = 1; wi < NWARP; wi++) v = fminf(v, smin[wi][t]);
        g_partial[(size_t)(b * JJ + jg * JT + t) * PC + pc] = v;
    }

    // ---- last-block finalize (fused MSE) ----
    __threadfence();
    __syncthreads();
    __shared__ unsigned s_last;
    if (t == 0) {
        unsigned c = atomicAdd(&g_count, 1u);
        s_last = (c == (unsigned)(GRID - 1)) ? 1u : 0u;
    }
    __syncthreads();
    if (s_last == 0u) return;

    // Last block: all partials globally visible. Batch loads (MLP) then reduce.
    const float4* gp = (const float4*)g_partial;
    float4 pv[TAILK];
    float  gv[TAILK];
#pragma unroll
    for (int k = 0; k < TAILK; k++) {
        int i = t + k * THREADS;
        bool ok = (i < NBJ);
        pv[k] = ok ? __ldcg(gp + i) : make_float4(0.f, 0.f, 0.f, 0.f);
        gv[k] = ok ? gt[i] : 0.f;
    }
    float s = 0.0f;
#pragma unroll
    for (int k = 0; k < TAILK; k++) {
        int i = t + k * THREADS;
        if (i < NBJ) {
            float m = fminf(fminf(pv[k].x, pv[k].y), fminf(pv[k].z, pv[k].w));
            m = fmaxf(m, 0.0f);
            float d = sqrtf(m) - gv[k];
            s = fmaf(d, d, s);
        }
    }
    // Deterministic fixed-order reduction.
    s += __shfl_xor_sync(0xFFFFFFFFu, s, 16);
    s += __shfl_xor_sync(0xFFFFFFFFu, s, 8);
    s += __shfl_xor_sync(0xFFFFFFFFu, s, 4);
    s += __shfl_xor_sync(0xFFFFFFFFu, s, 2);
    s += __shfl_xor_sync(0xFFFFFFFFu, s, 1);
    __shared__ float ssum[NWARP];
    if (l == 0) ssum[w] = s;
    __syncthreads();
    if (t == 0) {
        float tot = ssum[0];
#pragma unroll
        for (int wi = 1; wi < NWARP; wi++) tot += ssum[wi];
        out[0] = tot / (float)NBJ;
        g_count = 0;   // reset for next graph replay
    }
}

extern "C" void kernel_launch(void* const* d_in, const int* in_sizes, int n_in,
                              void* d_out, int out_size) {
    (void)in_sizes; (void)n_in; (void)out_size;
    const float* pred = (const float*)d_in[0];   // [64,42,3]
    const float* pts  = (const float*)d_in[1];   // [64,16384,3]
    const float* gt   = (const float*)d_in[2];   // [64,42]
    float* out = (float*)d_out;

    sdl_fused_kernel<<<GRID, THREADS>>>(pred, pts, gt, out);
}